// round 12
// baseline (speedup 1.0000x reference)
#include <cuda_runtime.h>
#include <cstdint>

#define NN 8192
#define DD 64
#define EPSF 1e-6f
#define PITCH_W 36    // 32-bit words per Z smem row (144B): conflict-free frags
#define APITCH_B 72   // bytes per A smem row (18 words): conflict-free LDS
#define T_U 0.0625f
#define L2E 1.44269504f
#define LN2 0.69314718f

// scratch (no allocations allowed)
__device__ double g_acc;
__device__ float g_pi[NN];    // sq_i + 2*eps*s_i + D*eps^2   (EXACT fp32)
__device__ float g_qa[NN*2];  // interleaved: (sq_j - 2*eps*s_j, alpha_j*log2e)

// ---------------------------------------------------------------------------
__global__ void prep_kernel(const float* __restrict__ Z,
                            const float* __restrict__ alpha) {
    if (blockIdx.x == 0 && threadIdx.x == 0) g_acc = 0.0;
    int w = (blockIdx.x * blockDim.x + threadIdx.x) >> 5;
    int lane = threadIdx.x & 31;
    if (w >= NN) return;
    float2 v = ((const float2*)(Z + (size_t)w * DD))[lane];
    float s = v.x + v.y;
    float sq = v.x * v.x + v.y * v.y;
#pragma unroll
    for (int off = 16; off; off >>= 1) {
        s  += __shfl_xor_sync(0xffffffffu, s, off);
        sq += __shfl_xor_sync(0xffffffffu, sq, off);
    }
    if (lane == 0) {
        g_pi[w] = sq + 2.0f * EPSF * s + (float)DD * EPSF * EPSF;
        g_qa[2 * w]     = sq - 2.0f * EPSF * s;
        g_qa[2 * w + 1] = alpha[w] * L2E;     // alpha in log2 units
    }
}

__device__ __forceinline__ uint32_t pack_bf16x2(float lo, float hi) {
    uint32_t r;  // first cvt source -> upper half
    asm("cvt.rn.bf16x2.f32 %0, %1, %2;" : "=r"(r) : "f"(hi), "f"(lo));
    return r;
}

__device__ __forceinline__ float sqrt_approx(float x) {
    float r;
    asm("sqrt.approx.f32 %0, %1;" : "=f"(r) : "f"(x));
    return r;
}

__device__ __forceinline__ float ex2f(float x) {
    float r;
    asm("ex2.approx.f32 %0, %1;" : "=f"(r) : "f"(x));
    return r;
}

__device__ __forceinline__ float log1p_poly32(float u) {
    return u * fmaf(u, fmaf(u, 0.33333333f, -0.5f), 1.0f);
}

// ---------------------------------------------------------------------------
// main: bf16 mma.sync gram (tile 128 x 64, K=64) + fused epilogue.
// A tile pre-staged to smem as BYTES (latency decoupling); ex2-based softplus.
// ---------------------------------------------------------------------------
#define SM_ZI   0
#define SM_ZJ   (128 * PITCH_W * 4)                   // 18432
#define SM_A    (SM_ZJ + 64 * PITCH_W * 4)            // 27648
#define SM_PI   (SM_A + 128 * APITCH_B)               // 36864
#define SM_QA   (SM_PI + 512)
#define SM_WS   (SM_QA + 512)
#define SM_TOT  (SM_WS + 16)

__global__ __launch_bounds__(128) void lsm_main(const int* __restrict__ A,
                                                const float* __restrict__ Z) {
    extern __shared__ __align__(16) char smem[];
    uint32_t* s_zi = (uint32_t*)(smem + SM_ZI);
    uint32_t* s_zj = (uint32_t*)(smem + SM_ZJ);
    char* sA = smem + SM_A;
    float* s_pi = (float*)(smem + SM_PI);
    float2* qaf2 = (float2*)(smem + SM_QA);
    float* s_ws = (float*)(smem + SM_WS);

    const int tid = (int)threadIdx.x;
    const int wid = tid >> 5, lane = tid & 31;
    const int g = lane >> 2, t = lane & 3;
    const int bi = blockIdx.y, bj = blockIdx.x;   // rows bi*128, cols bj*64
    const int wm = wid * 32;
    const bool diagblk = ((bj >> 1) == bi);

    // ---- stage A tile as bytes FIRST (max latency amortization) ----
    {
        const int4* Ap = (const int4*)(A + (size_t)(bi * 128) * NN + bj * 64);
#pragma unroll
        for (int it = 0; it < 16; ++it) {
            int idx = it * 128 + tid;
            int r = idx >> 4, c4 = idx & 15;
            int4 a = Ap[(size_t)r * (NN / 4) + c4];
            uint32_t packed = (uint32_t)a.x | ((uint32_t)a.y << 8) |
                              ((uint32_t)a.z << 16) | ((uint32_t)a.w << 24);
            *(uint32_t*)(sA + r * APITCH_B + c4 * 4) = packed;
        }
    }

    // ---- small arrays ----
    s_pi[tid] = g_pi[bi * 128 + tid];
    if (tid < 64) qaf2[tid] = ((const float2*)g_qa)[bj * 64 + tid];

    // ---- stage Z tiles as bf16 (rn) ----
    {
        const float4* src = (const float4*)(Z + (size_t)(bi * 128) * DD);
#pragma unroll
        for (int it = 0; it < 16; ++it) {
            int idx = it * 128 + tid;
            int r = idx >> 4, k4 = idx & 15;
            float4 v = src[(size_t)r * 16 + k4];
            *(uint2*)(s_zi + r * PITCH_W + k4 * 2) =
                make_uint2(pack_bf16x2(v.x, v.y), pack_bf16x2(v.z, v.w));
        }
        const float4* srcj = (const float4*)(Z + (size_t)(bj * 64) * DD);
#pragma unroll
        for (int it = 0; it < 8; ++it) {
            int idx = it * 128 + tid;
            int r = idx >> 4, k4 = idx & 15;
            float4 v = srcj[(size_t)r * 16 + k4];
            *(uint2*)(s_zj + r * PITCH_W + k4 * 2) =
                make_uint2(pack_bf16x2(v.x, v.y), pack_bf16x2(v.z, v.w));
        }
    }
    __syncthreads();

    // ---- preload ALL a-fragments (K=64 -> 4 k16-steps) ----
    uint32_t a[4][2][4];
#pragma unroll
    for (int ks = 0; ks < 4; ++ks) {
#pragma unroll
        for (int mf = 0; mf < 2; ++mf) {
            int r0 = wm + mf * 16 + g;
            const uint32_t* base = s_zi + ks * 8 + t;
            a[ks][mf][0] = base[r0 * PITCH_W];
            a[ks][mf][1] = base[(r0 + 8) * PITCH_W];
            a[ks][mf][2] = base[r0 * PITCH_W + 4];
            a[ks][mf][3] = base[(r0 + 8) * PITCH_W + 4];
        }
    }

    // per-thread row constants
    float pir[4];
#pragma unroll
    for (int mf = 0; mf < 2; ++mf)
#pragma unroll
        for (int rs = 0; rs < 2; ++rs)
            pir[mf * 2 + rs] = s_pi[wm + mf * 16 + rs * 8 + g];

    float llA = 0.0f;    // sum of A_ij * theta (log2 units)
    float llS = 0.0f;    // sum of softplus (natural units)
    float acc0[2][4], acc1[2][4];

#define DO_MMA(NF, ACC)                                                        \
    do {                                                                       \
        _Pragma("unroll")                                                      \
        for (int mf = 0; mf < 2; ++mf)                                         \
            _Pragma("unroll")                                                  \
            for (int e = 0; e < 4; ++e) ACC[mf][e] = 0.0f;                     \
        _Pragma("unroll")                                                      \
        for (int ks = 0; ks < 4; ++ks) {                                       \
            int c0 = (NF) * 8 + g;                                             \
            uint32_t b0 = s_zj[c0 * PITCH_W + ks * 8 + t];                     \
            uint32_t b1 = s_zj[c0 * PITCH_W + ks * 8 + t + 4];                 \
            _Pragma("unroll")                                                  \
            for (int mf = 0; mf < 2; ++mf) {                                   \
                asm volatile(                                                  \
                    "mma.sync.aligned.m16n8k16.row.col.f32.bf16.bf16.f32 "     \
                    "{%0,%1,%2,%3}, {%4,%5,%6,%7}, {%8,%9}, {%0,%1,%2,%3};"    \
                    : "+f"(ACC[mf][0]), "+f"(ACC[mf][1]),                      \
                      "+f"(ACC[mf][2]), "+f"(ACC[mf][3])                       \
                    : "r"(a[ks][mf][0]), "r"(a[ks][mf][1]),                    \
                      "r"(a[ks][mf][2]), "r"(a[ks][mf][3]),                    \
                      "r"(b0), "r"(b1));                                       \
            }                                                                  \
        }                                                                      \
    } while (0)

#define DO_EPI(NF, ACC)                                                        \
    do {                                                                       \
        float uarr[8];                                                         \
        float umax = 0.0f;                                                     \
        float2 qa0 = qaf2[(NF) * 8 + 2 * t];                                   \
        float2 qa1 = qaf2[(NF) * 8 + 2 * t + 1];                               \
        _Pragma("unroll")                                                      \
        for (int mf = 0; mf < 2; ++mf)                                         \
            _Pragma("unroll")                                                  \
            for (int rs = 0; rs < 2; ++rs) {                                   \
                int r = mf * 2 + rs;                                           \
                int i_loc = wm + mf * 16 + rs * 8 + g;                         \
                uint32_t av = *(const uint16_t*)(                              \
                    sA + i_loc * APITCH_B + (NF) * 8 + 2 * t);                 \
                float d20 = fmaf(-2.0f, ACC[mf][rs * 2 + 0], pir[r] + qa0.x);  \
                float d21 = fmaf(-2.0f, ACC[mf][rs * 2 + 1], pir[r] + qa1.x);  \
                float zd0 = sqrt_approx(fmaxf(d20, 0.0f));                     \
                float zd1 = sqrt_approx(fmaxf(d21, 0.0f));                     \
                float thl0 = fmaf(zd0, -L2E, qa0.y);                           \
                float thl1 = fmaf(zd1, -L2E, qa1.y);                           \
                float u0 = ex2f(thl0);                                         \
                float u1 = ex2f(thl1);                                         \
                uarr[r * 2] = u0; uarr[r * 2 + 1] = u1;                        \
                umax = fmaxf(umax, fmaxf(u0, u1));                             \
                llS += log1p_poly32(u0) + log1p_poly32(u1);                    \
                if (av & 0xFFu) llA += thl0;                                   \
                if (av >> 8)    llA += thl1;                                   \
            }                                                                  \
        if (__any_sync(0xffffffffu, umax > T_U)) {  /* rare */                 \
            _Pragma("unroll")                                                  \
            for (int e = 0; e < 8; ++e)                                        \
                if (uarr[e] > T_U)                                             \
                    llS += __logf(1.0f + uarr[e]) - log1p_poly32(uarr[e]);     \
        }                                                                      \
        if (diagblk) {                                                         \
            _Pragma("unroll")                                                  \
            for (int mf = 0; mf < 2; ++mf)                                     \
                _Pragma("unroll")                                              \
                for (int rs = 0; rs < 2; ++rs)                                 \
                    _Pragma("unroll")                                          \
                    for (int c = 0; c < 2; ++c) {                              \
                        int i_loc = wm + mf * 16 + rs * 8 + g;                 \
                        int ig = bi * 128 + i_loc;                             \
                        int jg = bj * 64 + (NF) * 8 + 2 * t + c;               \
                        if (ig == jg) {                                        \
                            float u = uarr[(mf * 2 + rs) * 2 + c];             \
                            /* subtract exactly what the main path added */    \
                            llS -= (u > T_U) ? __logf(1.0f + u)                \
                                             : log1p_poly32(u);               \
                        }                                                      \
                    }                                                          \
        }                                                                      \
    } while (0)

    // ---- skewed pipeline: MMA(nf) overlaps epilogue(nf-1) ----
    DO_MMA(0, acc0);
    DO_MMA(1, acc1);  DO_EPI(0, acc0);
    DO_MMA(2, acc0);  DO_EPI(1, acc1);
    DO_MMA(3, acc1);  DO_EPI(2, acc0);
    DO_MMA(4, acc0);  DO_EPI(3, acc1);
    DO_MMA(5, acc1);  DO_EPI(4, acc0);
    DO_MMA(6, acc0);  DO_EPI(5, acc1);
    DO_MMA(7, acc1);  DO_EPI(6, acc0);
    DO_EPI(7, acc1);

    float ll = 0.5f * (fmaf(llA, LN2, -llS));

    // ---- reduce + single double atomic per block ----
#pragma unroll
    for (int off = 16; off; off >>= 1) ll += __shfl_xor_sync(0xffffffffu, ll, off);
    if (lane == 0) s_ws[wid] = ll;
    __syncthreads();
    if (tid == 0)
        atomicAdd(&g_acc, (double)(s_ws[0] + s_ws[1] + s_ws[2] + s_ws[3]));
}

__global__ void finish_kernel(float* out) { out[0] = (float)g_acc; }

// ---------------------------------------------------------------------------
extern "C" void kernel_launch(void* const* d_in, const int* in_sizes, int n_in,
                              void* d_out, int out_size) {
    const int* A = nullptr;
    const float* alpha = nullptr;
    const float* Z = nullptr;
    for (int i = 0; i < n_in; ++i) {
        if (in_sizes[i] == NN) alpha = (const float*)d_in[i];
        else if (in_sizes[i] == NN * DD) Z = (const float*)d_in[i];
        else A = (const int*)d_in[i];
    }

    cudaFuncSetAttribute(lsm_main, cudaFuncAttributeMaxDynamicSharedMemorySize,
                         SM_TOT);

    prep_kernel<<<(NN * 32 + 255) / 256, 256>>>(Z, alpha);
    dim3 grid(NN / 64, NN / 128);
    lsm_main<<<grid, 128, SM_TOT>>>(A, Z);
    finish_kernel<<<1, 1>>>((float*)d_out);
}

// round 15
// speedup vs baseline: 1.1231x; 1.1231x over previous
#include <cuda_runtime.h>
#include <cstdint>

#define NN 8192
#define DD 64
#define EPSF 1e-6f
#define PITCH_W 36   // 32-bit words per smem row (144B): conflict-free frags
#define T_U 0.0625f
#define L2E 1.44269504f
#define LN2 0.69314718f
#define SQRT2_L2E 2.04027891f   // sqrt(2) * log2(e)

// scratch (no allocations allowed)
__device__ double g_acc;
__device__ float g_pi[NN];    // 0.5*(sq + 2*eps*s + D*eps^2)
__device__ float g_qa[NN*2];  // interleaved: (0.5*(sq - 2*eps*s), alpha*log2e)

// ---------------------------------------------------------------------------
__global__ void prep_kernel(const float* __restrict__ Z,
                            const float* __restrict__ alpha) {
    if (blockIdx.x == 0 && threadIdx.x == 0) g_acc = 0.0;
    int w = (blockIdx.x * blockDim.x + threadIdx.x) >> 5;
    int lane = threadIdx.x & 31;
    if (w >= NN) return;
    float2 v = ((const float2*)(Z + (size_t)w * DD))[lane];
    float s = v.x + v.y;
    float sq = v.x * v.x + v.y * v.y;
#pragma unroll
    for (int off = 16; off; off >>= 1) {
        s  += __shfl_xor_sync(0xffffffffu, s, off);
        sq += __shfl_xor_sync(0xffffffffu, sq, off);
    }
    if (lane == 0) {
        g_pi[w] = 0.5f * (sq + 2.0f * EPSF * s + (float)DD * EPSF * EPSF);
        g_qa[2 * w]     = 0.5f * (sq - 2.0f * EPSF * s);
        g_qa[2 * w + 1] = alpha[w] * L2E;     // alpha in log2 units
    }
}

__device__ __forceinline__ uint32_t pack_bf16x2(float lo, float hi) {
    uint32_t r;  // first cvt source -> upper half
    asm("cvt.rn.bf16x2.f32 %0, %1, %2;" : "=r"(r) : "f"(hi), "f"(lo));
    return r;
}

__device__ __forceinline__ float sqrt_approx(float x) {
    float r;
    asm("sqrt.approx.f32 %0, %1;" : "=f"(r) : "f"(x));
    return r;
}

__device__ __forceinline__ float ex2f(float x) {
    float r;
    asm("ex2.approx.f32 %0, %1;" : "=f"(r) : "f"(x));
    return r;
}

// ---------------------------------------------------------------------------
// main: bf16 mma.sync gram (tile 128 x 64, K=64).
// Zj staged NEGATED -> MMA yields -G; accumulator initialized to
// 0.5*pi + 0.5*qx, so post-MMA acc = d^2/2 directly. Linear softplus
// (log1p(u) ~= u) with exact ballot-gated correction for u > T_U.
// ---------------------------------------------------------------------------
__global__ __launch_bounds__(128) void lsm_main(const int* __restrict__ A,
                                                const float* __restrict__ Z) {
    extern __shared__ __align__(16) uint32_t smem[];
    uint32_t* s_zi = smem;                       // [128][PITCH_W] bf16x2 words
    uint32_t* s_zj = smem + 128 * PITCH_W;       // [64][PITCH_W], negated
    float* s_pi = (float*)(s_zj + 64 * PITCH_W); // [128] (half-pi)
    float* s_qa = s_pi + 128;                    // 64 float2
    float* s_ws = s_qa + 128;                    // [4]

    const int tid = (int)threadIdx.x;
    const int wid = tid >> 5, lane = tid & 31;
    const int g = lane >> 2, t = lane & 3;
    const int bi = blockIdx.y, bj = blockIdx.x;   // rows bi*128, cols bj*64
    const int wm = wid * 32;
    const bool diagblk = ((bj >> 1) == bi);

    // ---- stage small arrays ----
    s_pi[tid] = g_pi[bi * 128 + tid];
    if (tid < 64) ((float2*)s_qa)[tid] = ((const float2*)g_qa)[bj * 64 + tid];

    // ---- stage Z tiles as bf16; Zj negated via sign-bit XOR ----
    {
        const float4* src = (const float4*)(Z + (size_t)(bi * 128) * DD);
#pragma unroll
        for (int it = 0; it < 16; ++it) {
            int idx = it * 128 + tid;
            int r = idx >> 4, k4 = idx & 15;
            float4 v = src[(size_t)r * 16 + k4];
            *(uint2*)(s_zi + r * PITCH_W + k4 * 2) =
                make_uint2(pack_bf16x2(v.x, v.y), pack_bf16x2(v.z, v.w));
        }
        const float4* srcj = (const float4*)(Z + (size_t)(bj * 64) * DD);
#pragma unroll
        for (int it = 0; it < 8; ++it) {
            int idx = it * 128 + tid;
            int r = idx >> 4, k4 = idx & 15;
            float4 v = srcj[(size_t)r * 16 + k4];
            *(uint2*)(s_zj + r * PITCH_W + k4 * 2) =
                make_uint2(pack_bf16x2(v.x, v.y) ^ 0x80008000u,
                           pack_bf16x2(v.z, v.w) ^ 0x80008000u);
        }
    }
    __syncthreads();

    const float2* qaf2 = (const float2*)s_qa;

    // ---- preload ALL a-fragments (K=64 -> 4 k16-steps) ----
    uint32_t a[4][2][4];
#pragma unroll
    for (int ks = 0; ks < 4; ++ks) {
#pragma unroll
        for (int mf = 0; mf < 2; ++mf) {
            int r0 = wm + mf * 16 + g;
            const uint32_t* base = s_zi + ks * 8 + t;
            a[ks][mf][0] = base[r0 * PITCH_W];
            a[ks][mf][1] = base[(r0 + 8) * PITCH_W];
            a[ks][mf][2] = base[r0 * PITCH_W + 4];
            a[ks][mf][3] = base[(r0 + 8) * PITCH_W + 4];
        }
    }

    // per-thread row constants (half-pi) + A row pointers
    float pir[4];
    const int2* ar[4];
#pragma unroll
    for (int mf = 0; mf < 2; ++mf)
#pragma unroll
        for (int rs = 0; rs < 2; ++rs) {
            int r = mf * 2 + rs;
            int i_loc = wm + mf * 16 + rs * 8 + g;
            pir[r] = s_pi[i_loc];
            ar[r] = (const int2*)(A + (size_t)(bi * 128 + i_loc) * NN + bj * 64);
        }

    float llA = 0.0f;    // sum of A_ij * theta (log2 units)
    float llS = 0.0f;    // sum of softplus (natural units)
    float acc0[2][4], acc1[2][4];

    // ---- MMA with accumulator init = 0.5*pi + 0.5*qx ----
#define DO_MMA(NF, ACC)                                                        \
    do {                                                                       \
        float qh0 = qaf2[(NF) * 8 + 2 * t].x;                                  \
        float qh1 = qaf2[(NF) * 8 + 2 * t + 1].x;                              \
        _Pragma("unroll")                                                      \
        for (int mf = 0; mf < 2; ++mf) {                                       \
            ACC[mf][0] = pir[mf * 2] + qh0;                                    \
            ACC[mf][1] = pir[mf * 2] + qh1;                                    \
            ACC[mf][2] = pir[mf * 2 + 1] + qh0;                                \
            ACC[mf][3] = pir[mf * 2 + 1] + qh1;                                \
        }                                                                      \
        _Pragma("unroll")                                                      \
        for (int ks = 0; ks < 4; ++ks) {                                       \
            int c0 = (NF) * 8 + g;                                             \
            uint32_t b0 = s_zj[c0 * PITCH_W + ks * 8 + t];                     \
            uint32_t b1 = s_zj[c0 * PITCH_W + ks * 8 + t + 4];                 \
            _Pragma("unroll")                                                  \
            for (int mf = 0; mf < 2; ++mf) {                                   \
                asm volatile(                                                  \
                    "mma.sync.aligned.m16n8k16.row.col.f32.bf16.bf16.f32 "     \
                    "{%0,%1,%2,%3}, {%4,%5,%6,%7}, {%8,%9}, {%0,%1,%2,%3};"    \
                    : "+f"(ACC[mf][0]), "+f"(ACC[mf][1]),                      \
                      "+f"(ACC[mf][2]), "+f"(ACC[mf][3])                       \
                    : "r"(a[ks][mf][0]), "r"(a[ks][mf][1]),                    \
                      "r"(a[ks][mf][2]), "r"(a[ks][mf][3]),                    \
                      "r"(b0), "r"(b1));                                       \
            }                                                                  \
        }                                                                      \
    } while (0)

    // ---- lean epilogue: acc = d^2/2 already ----
#define DO_EPI(NF, ACC)                                                        \
    do {                                                                       \
        float uarr[8];                                                         \
        float umax = 0.0f;                                                     \
        float qy0 = qaf2[(NF) * 8 + 2 * t].y;                                  \
        float qy1 = qaf2[(NF) * 8 + 2 * t + 1].y;                              \
        _Pragma("unroll")                                                      \
        for (int mf = 0; mf < 2; ++mf)                                         \
            _Pragma("unroll")                                                  \
            for (int rs = 0; rs < 2; ++rs) {                                   \
                int r = mf * 2 + rs;                                           \
                int2 a2 = ar[r][(NF) * 4 + t];                                 \
                float z0 = sqrt_approx(fmaxf(ACC[mf][rs * 2 + 0], 0.0f));      \
                float z1 = sqrt_approx(fmaxf(ACC[mf][rs * 2 + 1], 0.0f));      \
                float thl0 = fmaf(z0, -SQRT2_L2E, qy0);                        \
                float thl1 = fmaf(z1, -SQRT2_L2E, qy1);                        \
                float u0 = ex2f(thl0);                                         \
                float u1 = ex2f(thl1);                                         \
                uarr[r * 2] = u0; uarr[r * 2 + 1] = u1;                        \
                umax = fmaxf(umax, fmaxf(u0, u1));                             \
                llS += u0 + u1;                                                \
                if (a2.x) llA += thl0;                                         \
                if (a2.y) llA += thl1;                                         \
            }                                                                  \
        if (__any_sync(0xffffffffu, umax > T_U)) {  /* ~never off-diag */      \
            _Pragma("unroll")                                                  \
            for (int e = 0; e < 8; ++e)                                        \
                if (uarr[e] > T_U)                                             \
                    llS += __logf(1.0f + uarr[e]) - uarr[e];                   \
        }                                                                      \
        if (diagblk) {                                                         \
            _Pragma("unroll")                                                  \
            for (int mf = 0; mf < 2; ++mf)                                     \
                _Pragma("unroll")                                              \
                for (int rs = 0; rs < 2; ++rs)                                 \
                    _Pragma("unroll")                                          \
                    for (int c = 0; c < 2; ++c) {                              \
                        int i_loc = wm + mf * 16 + rs * 8 + g;                 \
                        int ig = bi * 128 + i_loc;                             \
                        int jg = bj * 64 + (NF) * 8 + 2 * t + c;               \
                        if (ig == jg) {                                        \
                            float u = uarr[(mf * 2 + rs) * 2 + c];             \
                            /* subtract exactly what the main path added */    \
                            llS -= (u > T_U) ? __logf(1.0f + u) : u;           \
                        }                                                      \
                    }                                                          \
        }                                                                      \
    } while (0)

    // ---- skewed pipeline: MMA(nf) overlaps epilogue(nf-1) ----
    DO_MMA(0, acc0);
    DO_MMA(1, acc1);  DO_EPI(0, acc0);
    DO_MMA(2, acc0);  DO_EPI(1, acc1);
    DO_MMA(3, acc1);  DO_EPI(2, acc0);
    DO_MMA(4, acc0);  DO_EPI(3, acc1);
    DO_MMA(5, acc1);  DO_EPI(4, acc0);
    DO_MMA(6, acc0);  DO_EPI(5, acc1);
    DO_MMA(7, acc1);  DO_EPI(6, acc0);
    DO_EPI(7, acc1);

    float ll = 0.5f * (fmaf(llA, LN2, -llS));

    // ---- reduce + single double atomic per block ----
#pragma unroll
    for (int off = 16; off; off >>= 1) ll += __shfl_xor_sync(0xffffffffu, ll, off);
    if (lane == 0) s_ws[wid] = ll;
    __syncthreads();
    if (tid == 0)
        atomicAdd(&g_acc, (double)(s_ws[0] + s_ws[1] + s_ws[2] + s_ws[3]));
}

__global__ void finish_kernel(float* out) { out[0] = (float)g_acc; }

// ---------------------------------------------------------------------------
extern "C" void kernel_launch(void* const* d_in, const int* in_sizes, int n_in,
                              void* d_out, int out_size) {
    const int* A = nullptr;
    const float* alpha = nullptr;
    const float* Z = nullptr;
    for (int i = 0; i < n_in; ++i) {
        if (in_sizes[i] == NN) alpha = (const float*)d_in[i];
        else if (in_sizes[i] == NN * DD) Z = (const float*)d_in[i];
        else A = (const int*)d_in[i];
    }

    const int smem_bytes = (128 * PITCH_W + 64 * PITCH_W + 128 + 128 + 4) * 4;
    cudaFuncSetAttribute(lsm_main, cudaFuncAttributeMaxDynamicSharedMemorySize,
                         smem_bytes);

    prep_kernel<<<(NN * 32 + 255) / 256, 256>>>(Z, alpha);
    dim3 grid(NN / 64, NN / 128);
    lsm_main<<<grid, 128, smem_bytes>>>(A, Z);
    finish_kernel<<<1, 1>>>((float*)d_out);
}